// round 8
// baseline (speedup 1.0000x reference)
#include <cuda_runtime.h>

// Problem constants
#define BB 2
#define CC 64
#define HH 64
#define WW 128
#define HWN (HH*WW)         // 8192
#define NXG 512
#define NYG 512
#define NCELL (NXG*NYG)     // 262144
#define SCH 32              // near-chunk slots (dynamic count may use fewer)
#define NCHUNK 256
#define POS_INF (3.402823466e38f)
#define IDX_INF 0x7fffffff

// Scratch (device globals — no runtime allocation allowed)
__device__ float  g_fvT[BB*HWN*CC];          // transposed features (B, HW, C)
__device__ float4 g_nearc[BB*HWN];           // compacted valid near pts {x,y,z,|n|^2}
__device__ int    g_near_idx[BB*HWN];        // original index of compacted near pts
__device__ int    g_near_cnt[BB];
__device__ int    g_far_idx[BB*HWN];         // compacted valid+in-range far point indices
__device__ int    g_far_cnt[BB];
__device__ float4 g_ps[BB*SCH*HWN];          // partial top-3 d2 {s0,s1,s2,-} [b][chunk][slot]
__device__ int4   g_pi[BB*SCH*HWN];          // partial top-3 compacted idx {i0,i1,i2,-}
__device__ float  g_cnt[BB*NCELL];           // per-cell point counts

// Sorted-insert of smallest-3, strict '<' so earlier indices win ties
// (ordered compaction + ascending chunk order -> matches stable top_k)
#define INS(val, jj) do {                                             \
    if ((val) < s2) {                                                 \
        if ((val) < s1) {                                             \
            s2 = s1; i2 = i1;                                         \
            if ((val) < s0) { s1 = s0; i1 = i0; s0 = (val); i0 = (jj); } \
            else            { s1 = (val); i1 = (jj); }                \
        } else { s2 = (val); i2 = (jj); }                             \
    }                                                                 \
} while (0)

__device__ __forceinline__ int cell_x(float x) { return (int)floorf(__fdiv_rn(x, 0.1f)); }
__device__ __forceinline__ int cell_y(float y) { return (int)floorf(__fdiv_rn(__fsub_rn(y, -25.6f), 0.1f)); }

// |p|^2 with the reference's rounding: ((x*x + y*y) + z*z), no fma contraction
__device__ __forceinline__ float sqnorm_ref(float x, float y, float z) {
    return __fadd_rn(__fadd_rn(__fmul_rn(x, x), __fmul_rn(y, y)), __fmul_rn(z, z));
}

// GEMM-replica pair distance: acc = rn(a0*b0); acc = fma(a1,b1,acc); acc = fma(a2,b2,acc);
// d2 = rn( rn(fsq+nsq) - acc ).  Pre-doubled f is bit-equal to the alpha=2 folded GEMM.
__device__ __forceinline__ float d2_ref(float fx2, float fy2, float fz2, float fsq,
                                        float nx, float ny, float nz, float nsq) {
    float acc = __fmul_rn(fx2, nx);
    acc = __fmaf_rn(fy2, ny, acc);
    acc = __fmaf_rn(fz2, nz, acc);
    return __fsub_rn(__fadd_rn(fsq, nsq), acc);
}

// ---------------------------------------------------------------------------
// 0. transpose fv (B,C,HW) -> g_fvT (B,HW,C), smem-tiled, fully coalesced
// ---------------------------------------------------------------------------
__global__ void transpose_kernel(const float* __restrict__ fv) {
    __shared__ float tile[32][33];
    int b = blockIdx.z;
    int p0 = blockIdx.x * 32, c0 = blockIdx.y * 32;
    int tx = threadIdx.x, ty = threadIdx.y;      // 32 x 8
    #pragma unroll
    for (int i = ty; i < 32; i += 8)
        tile[i][tx] = fv[((size_t)b*CC + c0 + i) * HWN + p0 + tx];
    __syncthreads();
    #pragma unroll
    for (int i = ty; i < 32; i += 8)
        g_fvT[((size_t)b*HWN + p0 + i) * CC + c0 + tx] = tile[tx][i];
}

// ---------------------------------------------------------------------------
// 1. ordered compaction, ballot + block-scan (one block per batch).
//    Coalesced reads; stable order by original index.
// ---------------------------------------------------------------------------
__global__ void __launch_bounds__(256) compact_kernel(const float* __restrict__ pif,
                               const int*   __restrict__ mask,
                               const float* __restrict__ piff,
                               const int*   __restrict__ maskf) {
    int b = blockIdx.x;
    int tid = threadIdx.x;                       // 256
    int warp = tid >> 5, lane = tid & 31;
    __shared__ unsigned smask[256];              // validity masks, index-ordered chunks
    __shared__ int sscan[256];                   // inclusive scan of popcounts

    // ===== phase A: near (predicate = mask > 0) =====
    const int*   mn = mask + b * HWN;
    const float* pn = pif + (size_t)b * 4 * HWN;
    #pragma unroll 4
    for (int r = 0; r < 32; r++) {
        int p = r * 256 + tid;                   // coalesced
        unsigned m = __ballot_sync(0xffffffffu, mn[p] > 0);
        if (lane == 0) smask[r*8 + warp] = m;    // chunk key = p/32
    }
    __syncthreads();
    int own = __popc(smask[tid]);
    sscan[tid] = own;
    __syncthreads();
    #pragma unroll
    for (int off = 1; off < 256; off <<= 1) {
        int v = (tid >= off) ? sscan[tid - off] : 0;
        __syncthreads();
        sscan[tid] += v;
        __syncthreads();
    }
    if (tid == 255) g_near_cnt[b] = sscan[255];
    #pragma unroll 4
    for (int r = 0; r < 32; r++) {
        int p = r * 256 + tid;
        if (mn[p] > 0) {
            int key = r*8 + warp;
            unsigned m = smask[key];
            int rank = sscan[key] - __popc(m) + __popc(m & ((1u << lane) - 1u));
            float x = pn[p], y = pn[HWN + p], z = pn[2*HWN + p];
            g_nearc[b*HWN + rank] = make_float4(x, y, z, sqnorm_ref(x, y, z));
            g_near_idx[b*HWN + rank] = p;
        }
    }
    __syncthreads();

    // ===== phase B: far (predicate = mask > 0 && cell in range) =====
    const int*   mf  = maskf + b * HWN;
    const float* pff = piff + (size_t)b * 4 * HWN;
    #pragma unroll 4
    for (int r = 0; r < 32; r++) {
        int p = r * 256 + tid;
        bool v = mf[p] > 0;
        if (v) {
            int ix = cell_x(pff[p]), iy = cell_y(pff[HWN + p]);
            v = (ix >= 0 && ix < NXG && iy >= 0 && iy < NYG);
        }
        unsigned m = __ballot_sync(0xffffffffu, v);
        if (lane == 0) smask[r*8 + warp] = m;
    }
    __syncthreads();
    own = __popc(smask[tid]);
    sscan[tid] = own;
    __syncthreads();
    #pragma unroll
    for (int off = 1; off < 256; off <<= 1) {
        int v = (tid >= off) ? sscan[tid - off] : 0;
        __syncthreads();
        sscan[tid] += v;
        __syncthreads();
    }
    if (tid == 255) g_far_cnt[b] = sscan[255];
    #pragma unroll 4
    for (int r = 0; r < 32; r++) {
        int p = r * 256 + tid;
        int key = r*8 + warp;
        unsigned m = smask[key];
        if ((m >> lane) & 1u) {
            int rank = sscan[key] - __popc(m) + __popc(m & ((1u << lane) - 1u));
            g_far_idx[b*HWN + rank] = p;
        }
    }
}

// ---------------------------------------------------------------------------
// 2. kNN over compacted near points: thread = far point, small smem chunk
// ---------------------------------------------------------------------------
__global__ void __launch_bounds__(256) knn_kernel(const float* __restrict__ pif_far) {
    __shared__ float4 sh[NCHUNK];
    int b  = blockIdx.z;
    int ch = blockIdx.y;
    int nbase = ch * NCHUNK;
    int ncnt = g_near_cnt[b];
    if (nbase >= ncnt) return;
    if (blockIdx.x * 256 >= g_far_cnt[b]) return;

    int navail = min(NCHUNK, ncnt - nbase);
    int n8 = (navail + 7) & ~7;                  // pad to multiple of 8
    const float4* src = g_nearc + b*HWN + nbase;
    for (int i = threadIdx.x; i < n8; i += 256)
        sh[i] = (i < navail) ? src[i] : make_float4(0.f, 0.f, 0.f, 1e30f);
    __syncthreads();

    int slot = blockIdx.x * 256 + threadIdx.x;
    if (slot >= g_far_cnt[b]) return;
    int p = g_far_idx[b*HWN + slot];

    const float* pf = pif_far + (size_t)b * 4 * HWN;
    float x = pf[p], y = pf[HWN + p], z = pf[2*HWN + p];
    float fsq = sqnorm_ref(x, y, z);
    float fx2 = 2.0f * x, fy2 = 2.0f * y, fz2 = 2.0f * z;  // exact

    float s0 = POS_INF, s1 = POS_INF, s2 = POS_INF;
    int   i0 = 0, i1 = 0, i2 = 0;

    #pragma unroll 1
    for (int j = 0; j < n8; j += 8) {
        float d[8];
        #pragma unroll
        for (int u = 0; u < 8; u++) {
            float4 q = sh[j + u];
            d[u] = d2_ref(fx2, fy2, fz2, fsq, q.x, q.y, q.z, q.w);
        }
        float m = fminf(fminf(fminf(d[0], d[1]), fminf(d[2], d[3])),
                        fminf(fminf(d[4], d[5]), fminf(d[6], d[7])));
        if (m < s2) {   // rarely taken
            #pragma unroll
            for (int u = 0; u < 8; u++) INS(d[u], nbase + j + u);
        }
    }

    int base = (b*SCH + ch) * HWN + slot;
    g_ps[base] = make_float4(s0, s1, s2, 0.0f);
    g_pi[base] = make_int4(i0, i1, i2, 0);
}

// ---------------------------------------------------------------------------
// 3. fused scatter. blockIdx.z = 0: near points (64 lanes/pt).
//    blockIdx.z = 1: far points — warp-parallel top-3 merge (lane = chunk),
//    IDW weights (reference rounding), then 64-lane gather+scatter.
// ---------------------------------------------------------------------------
__global__ void __launch_bounds__(256) scatter_kernel(const float* __restrict__ pif_far,
                                                      float* __restrict__ out) {
    int b = blockIdx.y;
    int local = threadIdx.x >> 6;                // point-in-block 0..3
    int lane64 = threadIdx.x & 63;
    int slot = blockIdx.x * 4 + local;

    if (blockIdx.z == 0) {
        if (slot >= g_near_cnt[b]) return;
        float4 q = g_nearc[b*HWN + slot];
        int ix = cell_x(q.x), iy = cell_y(q.y);
        if (ix < 0 || ix >= NXG || iy < 0 || iy >= NYG) return;
        int cell = iy * NXG + ix;
        int p = g_near_idx[b*HWN + slot];
        if (lane64 == 0) atomicAdd(&g_cnt[b*NCELL + cell], 1.0f);
        float f = g_fvT[((size_t)b*HWN + p) * CC + lane64];   // coalesced
        atomicAdd(out + (size_t)b*CC*NCELL + (size_t)lane64*NCELL + cell, f);
        return;
    }

    // ---- far path ----
    __shared__ float sw[4][3];
    __shared__ int   si[4][3];
    __shared__ int   scell[4];

    int fcnt = g_far_cnt[b];
    bool active = slot < fcnt;
    int half = lane64 >> 5;                      // warp-half within the point
    int lane = lane64 & 31;                      // chunk id for half 0

    if (active && half == 0) {
        // lane = chunk; load this chunk's sorted top-3 partial (or sentinels)
        int ncnt = g_near_cnt[b];
        float a0 = POS_INF, a1 = POS_INF, a2 = POS_INF;
        int   c0 = IDX_INF,  c1 = IDX_INF,  c2 = IDX_INF;
        if (lane * NCHUNK < ncnt) {
            int base = (b*SCH + lane) * HWN + slot;
            float4 v = g_ps[base];
            int4  iv = g_pi[base];
            a0 = v.x; a1 = v.y; a2 = v.z;
            c0 = iv.x; c1 = iv.y; c2 = iv.z;
        }
        // 3-round warp argmin by (value, then compacted index) — identical to
        // sequential INS order (chunks partition ascending indices; within-chunk
        // triples are index-ordered on equal values).
        float S[3]; int I[3];
        #pragma unroll
        for (int k = 0; k < 3; k++) {
            float bv = a0; int bx = c0;
            #pragma unroll
            for (int off = 16; off; off >>= 1) {
                float ov = __shfl_down_sync(0xffffffffu, bv, off);
                int   ox = __shfl_down_sync(0xffffffffu, bx, off);
                if (ov < bv || (ov == bv && ox < bx)) { bv = ov; bx = ox; }
            }
            bv = __shfl_sync(0xffffffffu, bv, 0);
            bx = __shfl_sync(0xffffffffu, bx, 0);
            S[k] = bv; I[k] = bx;
            if (c0 == bx) {                      // unique index -> unique winner
                a0 = a1; c0 = c1; a1 = a2; c1 = c2;
                a2 = POS_INF; c2 = IDX_INF;
            }
        }
        if (lane == 0) {
            // IDW weights exactly as reference: r = 1/(d+1e-8); w = r/((r0+r1)+r2)
            float r0 = __fdiv_rn(1.0f, __fadd_rn(S[0], 1e-8f));
            float r1 = __fdiv_rn(1.0f, __fadd_rn(S[1], 1e-8f));
            float r2 = __fdiv_rn(1.0f, __fadd_rn(S[2], 1e-8f));
            float rs = __fadd_rn(__fadd_rn(r0, r1), r2);
            sw[local][0] = __fdiv_rn(r0, rs);
            sw[local][1] = __fdiv_rn(r1, rs);
            sw[local][2] = __fdiv_rn(r2, rs);
            si[local][0] = g_near_idx[b*HWN + I[0]];
            si[local][1] = g_near_idx[b*HWN + I[1]];
            si[local][2] = g_near_idx[b*HWN + I[2]];
            int p = g_far_idx[b*HWN + slot];
            const float* pf = pif_far + (size_t)b * 4 * HWN;
            int ix = cell_x(pf[p]), iy = cell_y(pf[HWN + p]);  // in range by compaction
            int cell = iy * NXG + ix;
            scell[local] = cell;
            atomicAdd(&g_cnt[b*NCELL + cell], 1.0f);
        }
    }
    __syncthreads();
    if (!active) return;

    float w0 = sw[local][0], w1 = sw[local][1], w2 = sw[local][2];
    int   j0 = si[local][0], j1 = si[local][1], j2 = si[local][2];
    const float* fT = g_fvT + (size_t)b*HWN*CC;
    // einsum order: (w0*g0 + w1*g1) + w2*g2, no fma
    float f = __fadd_rn(__fadd_rn(__fmul_rn(w0, fT[(size_t)j0*CC + lane64]),
                                  __fmul_rn(w1, fT[(size_t)j1*CC + lane64])),
                        __fmul_rn(w2, fT[(size_t)j2*CC + lane64]));
    atomicAdd(out + (size_t)b*CC*NCELL + (size_t)lane64*NCELL + scell[local], f);
}

// ---------------------------------------------------------------------------
// 4. divide: only cells with cnt >= 2 need a fixup
// ---------------------------------------------------------------------------
__global__ void div_kernel(float* __restrict__ out) {
    int t = blockIdx.x * blockDim.x + threadIdx.x;
    if (t >= BB*NCELL) return;
    float c = g_cnt[t];
    if (c >= 2.0f) {
        int b = t / NCELL, cell = t % NCELL;
        float* ob = out + (size_t)b * CC * NCELL + cell;
        #pragma unroll 8
        for (int ch = 0; ch < CC; ch++)
            ob[(size_t)ch * NCELL] = __fdiv_rn(ob[(size_t)ch * NCELL], c);
    }
}

extern "C" void kernel_launch(void* const* d_in, const int* in_sizes, int n_in,
                              void* d_out, int out_size) {
    const float* fv    = (const float*)d_in[0];   // (B,C,H,W)
    const float* pif   = (const float*)d_in[1];   // (B,4,H,W)
    const int*   mask  = (const int*)  d_in[2];   // (B,H,W)
    const float* piff  = (const float*)d_in[3];   // (B,4,H,W)
    const int*   maskf = (const int*)  d_in[4];   // (B,H,W)
    float* out = (float*)d_out;                   // (B,C,NY,NX)

    void* p_cnt = nullptr;
    cudaGetSymbolAddress(&p_cnt, g_cnt);

    cudaMemsetAsync(d_out, 0, (size_t)BB*CC*NCELL*sizeof(float));
    cudaMemsetAsync(p_cnt, 0, (size_t)BB*NCELL*sizeof(float));

    transpose_kernel<<<dim3(HWN/32, CC/32, BB), dim3(32, 8)>>>(fv);
    compact_kernel<<<BB, 256>>>(pif, mask, piff, maskf);

    knn_kernel<<<dim3(HWN/256, SCH, BB), 256>>>(piff);

    scatter_kernel<<<dim3(HWN/4, BB, 2), 256>>>(piff, out);

    div_kernel<<<(BB*NCELL + 255)/256, 256>>>(out);
}

// round 9
// speedup vs baseline: 1.0328x; 1.0328x over previous
#include <cuda_runtime.h>

// Problem constants
#define BB 2
#define CC 64
#define HH 64
#define WW 128
#define HWN (HH*WW)         // 8192
#define NXG 512
#define NYG 512
#define NCELL (NXG*NYG)     // 262144
#define SCH 32              // near-chunk slots (dynamic count may use fewer)
#define NCHUNK 256
#define POS_INF (3.402823466e38f)
#define IDX_INF 0x7fffffff

// prep_kernel block-range dispatch
#define ZOUT_BLKS 4096      // (BB*CC*NCELL/4) / (256*8)
#define ZCNT_BLKS 64        // (BB*NCELL/4) / (256*8)
#define TR_BLKS   1024      // (HWN/32) * (CC/32) * BB
#define CP_BLKS   BB
#define PREP_BLKS (ZOUT_BLKS + ZCNT_BLKS + TR_BLKS + CP_BLKS)

// Scratch (device globals — no runtime allocation allowed)
__device__ float  g_fvT[BB*HWN*CC];          // transposed features (B, HW, C)
__device__ float4 g_nearc[BB*HWN];           // compacted valid near pts {x,y,z,|n|^2}
__device__ int    g_near_idx[BB*HWN];        // original index of compacted near pts
__device__ int    g_near_cnt[BB];
__device__ int    g_far_idx[BB*HWN];         // compacted valid+in-range far point indices
__device__ int    g_far_cnt[BB];
__device__ float4 g_ps[BB*SCH*HWN];          // partial top-3 d2 {s0,s1,s2,-} [b][chunk][slot]
__device__ int4   g_pi[BB*SCH*HWN];          // partial top-3 compacted idx {i0,i1,i2,-}
__device__ float  g_cnt[BB*NCELL];           // per-cell point counts

// Sorted-insert of smallest-3, strict '<' so earlier indices win ties
#define INS(val, jj) do {                                             \
    if ((val) < s2) {                                                 \
        if ((val) < s1) {                                             \
            s2 = s1; i2 = i1;                                         \
            if ((val) < s0) { s1 = s0; i1 = i0; s0 = (val); i0 = (jj); } \
            else            { s1 = (val); i1 = (jj); }                \
        } else { s2 = (val); i2 = (jj); }                             \
    }                                                                 \
} while (0)

__device__ __forceinline__ int cell_x(float x) { return (int)floorf(__fdiv_rn(x, 0.1f)); }
__device__ __forceinline__ int cell_y(float y) { return (int)floorf(__fdiv_rn(__fsub_rn(y, -25.6f), 0.1f)); }

// |p|^2 with the reference's rounding: ((x*x + y*y) + z*z), no fma contraction
__device__ __forceinline__ float sqnorm_ref(float x, float y, float z) {
    return __fadd_rn(__fadd_rn(__fmul_rn(x, x), __fmul_rn(y, y)), __fmul_rn(z, z));
}

// GEMM-replica pair distance: acc = rn(a0*b0); acc = fma(a1,b1,acc); acc = fma(a2,b2,acc);
// d2 = rn( rn(fsq+nsq) - acc ).  Pre-doubled f is bit-equal to the alpha=2 folded GEMM.
__device__ __forceinline__ float d2_ref(float fx2, float fy2, float fz2, float fsq,
                                        float nx, float ny, float nz, float nsq) {
    float acc = __fmul_rn(fx2, nx);
    acc = __fmaf_rn(fy2, ny, acc);
    acc = __fmaf_rn(fz2, nz, acc);
    return __fsub_rn(__fadd_rn(fsq, nsq), acc);
}

// ---------------------------------------------------------------------------
// 1. prep: ONE launch doing 4 independent jobs, dispatched by block range:
//    [0, 4096)            zero d_out (float4, coalesced)
//    [4096, 4160)         zero g_cnt
//    [4160, 5184)         transpose fv (B,C,HW) -> g_fvT (B,HW,C)
//    [5184, 5186)         ordered ballot/scan compaction (1 block per batch)
// ---------------------------------------------------------------------------
__global__ void __launch_bounds__(256) prep_kernel(const float* __restrict__ fv,
                                                   const float* __restrict__ pif,
                                                   const int*   __restrict__ mask,
                                                   const float* __restrict__ piff,
                                                   const int*   __restrict__ maskf,
                                                   float* __restrict__ out) {
    int bid = blockIdx.x;
    int tid = threadIdx.x;

    if (bid < ZOUT_BLKS) {                       // ---- zero d_out ----
        float4* o4 = (float4*)out;
        size_t base = (size_t)bid * 2048 + tid;
        const float4 z = make_float4(0.f, 0.f, 0.f, 0.f);
        #pragma unroll
        for (int i = 0; i < 8; i++)
            o4[base + (size_t)i * 256] = z;
        return;
    }
    bid -= ZOUT_BLKS;

    if (bid < ZCNT_BLKS) {                       // ---- zero g_cnt ----
        float4* c4 = (float4*)g_cnt;
        size_t base = (size_t)bid * 2048 + tid;
        const float4 z = make_float4(0.f, 0.f, 0.f, 0.f);
        #pragma unroll
        for (int i = 0; i < 8; i++)
            c4[base + (size_t)i * 256] = z;
        return;
    }
    bid -= ZCNT_BLKS;

    if (bid < TR_BLKS) {                         // ---- transpose ----
        __shared__ float tile[32][33];
        int b  = bid / ((HWN/32) * (CC/32));
        int r  = bid % ((HWN/32) * (CC/32));
        int c0 = (r / (HWN/32)) * 32;
        int p0 = (r % (HWN/32)) * 32;
        int tx = tid & 31, ty = tid >> 5;        // 32 x 8
        #pragma unroll
        for (int i = ty; i < 32; i += 8)
            tile[i][tx] = fv[((size_t)b*CC + c0 + i) * HWN + p0 + tx];
        __syncthreads();
        #pragma unroll
        for (int i = ty; i < 32; i += 8)
            g_fvT[((size_t)b*HWN + p0 + i) * CC + c0 + tx] = tile[tx][i];
        return;
    }
    bid -= TR_BLKS;

    // ---- compaction (1 block per batch), ballot + block scan ----
    int b = bid;
    int warp = tid >> 5, lane = tid & 31;
    __shared__ unsigned smask[256];              // validity masks, index-ordered chunks
    __shared__ int sscan[256];                   // inclusive scan of popcounts

    // ===== phase A: near (predicate = mask > 0) =====
    const int*   mn = mask + b * HWN;
    const float* pn = pif + (size_t)b * 4 * HWN;
    #pragma unroll 4
    for (int r = 0; r < 32; r++) {
        int p = r * 256 + tid;                   // coalesced
        unsigned m = __ballot_sync(0xffffffffu, mn[p] > 0);
        if (lane == 0) smask[r*8 + warp] = m;    // chunk key = p/32
    }
    __syncthreads();
    sscan[tid] = __popc(smask[tid]);
    __syncthreads();
    #pragma unroll
    for (int off = 1; off < 256; off <<= 1) {
        int v = (tid >= off) ? sscan[tid - off] : 0;
        __syncthreads();
        sscan[tid] += v;
        __syncthreads();
    }
    if (tid == 255) g_near_cnt[b] = sscan[255];
    #pragma unroll 4
    for (int r = 0; r < 32; r++) {
        int p = r * 256 + tid;
        if (mn[p] > 0) {
            int key = r*8 + warp;
            unsigned m = smask[key];
            int rank = sscan[key] - __popc(m) + __popc(m & ((1u << lane) - 1u));
            float x = pn[p], y = pn[HWN + p], z = pn[2*HWN + p];
            g_nearc[b*HWN + rank] = make_float4(x, y, z, sqnorm_ref(x, y, z));
            g_near_idx[b*HWN + rank] = p;
        }
    }
    __syncthreads();

    // ===== phase B: far (predicate = mask > 0 && cell in range) =====
    const int*   mf  = maskf + b * HWN;
    const float* pff = piff + (size_t)b * 4 * HWN;
    #pragma unroll 4
    for (int r = 0; r < 32; r++) {
        int p = r * 256 + tid;
        bool v = mf[p] > 0;
        if (v) {
            int ix = cell_x(pff[p]), iy = cell_y(pff[HWN + p]);
            v = (ix >= 0 && ix < NXG && iy >= 0 && iy < NYG);
        }
        unsigned m = __ballot_sync(0xffffffffu, v);
        if (lane == 0) smask[r*8 + warp] = m;
    }
    __syncthreads();
    sscan[tid] = __popc(smask[tid]);
    __syncthreads();
    #pragma unroll
    for (int off = 1; off < 256; off <<= 1) {
        int v = (tid >= off) ? sscan[tid - off] : 0;
        __syncthreads();
        sscan[tid] += v;
        __syncthreads();
    }
    if (tid == 255) g_far_cnt[b] = sscan[255];
    #pragma unroll 4
    for (int r = 0; r < 32; r++) {
        int p = r * 256 + tid;
        int key = r*8 + warp;
        unsigned m = smask[key];
        if ((m >> lane) & 1u) {
            int rank = sscan[key] - __popc(m) + __popc(m & ((1u << lane) - 1u));
            g_far_idx[b*HWN + rank] = p;
        }
    }
}

// ---------------------------------------------------------------------------
// 2. kNN over compacted near points: thread = far point, small smem chunk
// ---------------------------------------------------------------------------
__global__ void __launch_bounds__(256) knn_kernel(const float* __restrict__ pif_far) {
    __shared__ float4 sh[NCHUNK];
    int b  = blockIdx.z;
    int ch = blockIdx.y;
    int nbase = ch * NCHUNK;
    int ncnt = g_near_cnt[b];
    if (nbase >= ncnt) return;
    if (blockIdx.x * 256 >= g_far_cnt[b]) return;

    int navail = min(NCHUNK, ncnt - nbase);
    int n8 = (navail + 7) & ~7;                  // pad to multiple of 8
    const float4* src = g_nearc + b*HWN + nbase;
    for (int i = threadIdx.x; i < n8; i += 256)
        sh[i] = (i < navail) ? src[i] : make_float4(0.f, 0.f, 0.f, 1e30f);
    __syncthreads();

    int slot = blockIdx.x * 256 + threadIdx.x;
    if (slot >= g_far_cnt[b]) return;
    int p = g_far_idx[b*HWN + slot];

    const float* pf = pif_far + (size_t)b * 4 * HWN;
    float x = pf[p], y = pf[HWN + p], z = pf[2*HWN + p];
    float fsq = sqnorm_ref(x, y, z);
    float fx2 = 2.0f * x, fy2 = 2.0f * y, fz2 = 2.0f * z;  // exact

    float s0 = POS_INF, s1 = POS_INF, s2 = POS_INF;
    int   i0 = 0, i1 = 0, i2 = 0;

    #pragma unroll 1
    for (int j = 0; j < n8; j += 8) {
        float d[8];
        #pragma unroll
        for (int u = 0; u < 8; u++) {
            float4 q = sh[j + u];
            d[u] = d2_ref(fx2, fy2, fz2, fsq, q.x, q.y, q.z, q.w);
        }
        float m = fminf(fminf(fminf(d[0], d[1]), fminf(d[2], d[3])),
                        fminf(fminf(d[4], d[5]), fminf(d[6], d[7])));
        if (m < s2) {   // rarely taken
            #pragma unroll
            for (int u = 0; u < 8; u++) INS(d[u], nbase + j + u);
        }
    }

    int base = (b*SCH + ch) * HWN + slot;
    g_ps[base] = make_float4(s0, s1, s2, 0.0f);
    g_pi[base] = make_int4(i0, i1, i2, 0);
}

// ---------------------------------------------------------------------------
// 3. fused scatter. blockIdx.z = 0: near points (64 lanes/pt).
//    blockIdx.z = 1: far points — warp-parallel top-3 merge (lane = chunk),
//    IDW weights (reference rounding), then 64-lane gather+scatter.
// ---------------------------------------------------------------------------
__global__ void __launch_bounds__(256) scatter_kernel(const float* __restrict__ pif_far,
                                                      float* __restrict__ out) {
    int b = blockIdx.y;
    int local = threadIdx.x >> 6;                // point-in-block 0..3
    int lane64 = threadIdx.x & 63;
    int slot = blockIdx.x * 4 + local;

    if (blockIdx.z == 0) {
        if (slot >= g_near_cnt[b]) return;
        float4 q = g_nearc[b*HWN + slot];
        int ix = cell_x(q.x), iy = cell_y(q.y);
        if (ix < 0 || ix >= NXG || iy < 0 || iy >= NYG) return;
        int cell = iy * NXG + ix;
        int p = g_near_idx[b*HWN + slot];
        if (lane64 == 0) atomicAdd(&g_cnt[b*NCELL + cell], 1.0f);
        float f = g_fvT[((size_t)b*HWN + p) * CC + lane64];   // coalesced
        atomicAdd(out + (size_t)b*CC*NCELL + (size_t)lane64*NCELL + cell, f);
        return;
    }

    // ---- far path ----
    __shared__ float sw[4][3];
    __shared__ int   si[4][3];
    __shared__ int   scell[4];

    int fcnt = g_far_cnt[b];
    bool active = slot < fcnt;
    int half = lane64 >> 5;                      // warp-half within the point
    int lane = lane64 & 31;                      // chunk id for half 0

    if (active && half == 0) {
        // lane = chunk; load this chunk's sorted top-3 partial (or sentinels)
        int ncnt = g_near_cnt[b];
        float a0 = POS_INF, a1 = POS_INF, a2 = POS_INF;
        int   c0 = IDX_INF,  c1 = IDX_INF,  c2 = IDX_INF;
        if (lane * NCHUNK < ncnt) {
            int base = (b*SCH + lane) * HWN + slot;
            float4 v = g_ps[base];
            int4  iv = g_pi[base];
            a0 = v.x; a1 = v.y; a2 = v.z;
            c0 = iv.x; c1 = iv.y; c2 = iv.z;
        }
        // 3-round warp argmin by (value, then compacted index) — identical to
        // sequential INS order (chunks partition ascending indices; within-chunk
        // triples are index-ordered on equal values).
        float S[3]; int I[3];
        #pragma unroll
        for (int k = 0; k < 3; k++) {
            float bv = a0; int bx = c0;
            #pragma unroll
            for (int off = 16; off; off >>= 1) {
                float ov = __shfl_down_sync(0xffffffffu, bv, off);
                int   ox = __shfl_down_sync(0xffffffffu, bx, off);
                if (ov < bv || (ov == bv && ox < bx)) { bv = ov; bx = ox; }
            }
            bv = __shfl_sync(0xffffffffu, bv, 0);
            bx = __shfl_sync(0xffffffffu, bx, 0);
            S[k] = bv; I[k] = bx;
            if (c0 == bx) {                      // unique index -> unique winner
                a0 = a1; c0 = c1; a1 = a2; c1 = c2;
                a2 = POS_INF; c2 = IDX_INF;
            }
        }
        if (lane == 0) {
            // IDW weights exactly as reference: r = 1/(d+1e-8); w = r/((r0+r1)+r2)
            float r0 = __fdiv_rn(1.0f, __fadd_rn(S[0], 1e-8f));
            float r1 = __fdiv_rn(1.0f, __fadd_rn(S[1], 1e-8f));
            float r2 = __fdiv_rn(1.0f, __fadd_rn(S[2], 1e-8f));
            float rs = __fadd_rn(__fadd_rn(r0, r1), r2);
            sw[local][0] = __fdiv_rn(r0, rs);
            sw[local][1] = __fdiv_rn(r1, rs);
            sw[local][2] = __fdiv_rn(r2, rs);
            si[local][0] = g_near_idx[b*HWN + I[0]];
            si[local][1] = g_near_idx[b*HWN + I[1]];
            si[local][2] = g_near_idx[b*HWN + I[2]];
            int p = g_far_idx[b*HWN + slot];
            const float* pf = pif_far + (size_t)b * 4 * HWN;
            int ix = cell_x(pf[p]), iy = cell_y(pf[HWN + p]);  // in range by compaction
            int cell = iy * NXG + ix;
            scell[local] = cell;
            atomicAdd(&g_cnt[b*NCELL + cell], 1.0f);
        }
    }
    __syncthreads();
    if (!active) return;

    float w0 = sw[local][0], w1 = sw[local][1], w2 = sw[local][2];
    int   j0 = si[local][0], j1 = si[local][1], j2 = si[local][2];
    const float* fT = g_fvT + (size_t)b*HWN*CC;
    // einsum order: (w0*g0 + w1*g1) + w2*g2, no fma
    float f = __fadd_rn(__fadd_rn(__fmul_rn(w0, fT[(size_t)j0*CC + lane64]),
                                  __fmul_rn(w1, fT[(size_t)j1*CC + lane64])),
                        __fmul_rn(w2, fT[(size_t)j2*CC + lane64]));
    atomicAdd(out + (size_t)b*CC*NCELL + (size_t)lane64*NCELL + scell[local], f);
}

// ---------------------------------------------------------------------------
// 4. divide: only cells with cnt >= 2 need a fixup
// ---------------------------------------------------------------------------
__global__ void div_kernel(float* __restrict__ out) {
    int t = blockIdx.x * blockDim.x + threadIdx.x;
    if (t >= BB*NCELL) return;
    float c = g_cnt[t];
    if (c >= 2.0f) {
        int b = t / NCELL, cell = t % NCELL;
        float* ob = out + (size_t)b * CC * NCELL + cell;
        #pragma unroll 8
        for (int ch = 0; ch < CC; ch++)
            ob[(size_t)ch * NCELL] = __fdiv_rn(ob[(size_t)ch * NCELL], c);
    }
}

extern "C" void kernel_launch(void* const* d_in, const int* in_sizes, int n_in,
                              void* d_out, int out_size) {
    const float* fv    = (const float*)d_in[0];   // (B,C,H,W)
    const float* pif   = (const float*)d_in[1];   // (B,4,H,W)
    const int*   mask  = (const int*)  d_in[2];   // (B,H,W)
    const float* piff  = (const float*)d_in[3];   // (B,4,H,W)
    const int*   maskf = (const int*)  d_in[4];   // (B,H,W)
    float* out = (float*)d_out;                   // (B,C,NY,NX)

    prep_kernel<<<PREP_BLKS, 256>>>(fv, pif, mask, piff, maskf, out);

    knn_kernel<<<dim3(HWN/256, SCH, BB), 256>>>(piff);

    scatter_kernel<<<dim3(HWN/4, BB, 2), 256>>>(piff, out);

    div_kernel<<<(BB*NCELL + 255)/256, 256>>>(out);
}

// round 11
// speedup vs baseline: 1.0942x; 1.0594x over previous
#include <cuda_runtime.h>

// Problem constants
#define BB 2
#define CC 64
#define HH 64
#define WW 128
#define HWN (HH*WW)         // 8192
#define NXG 512
#define NYG 512
#define NCELL (NXG*NYG)     // 262144
#define SCH 32              // near-chunk slots (dynamic count may use fewer)
#define NCHUNK 256
#define POS_INF (3.402823466e38f)
#define IDX_INF 0x7fffffff

// prep_kernel block-range dispatch
#define ZOUT_BLKS 4096      // (BB*CC*NCELL/4) / (256*8)
#define TR_BLKS   1024      // (HWN/32) * (CC/32) * BB
#define CP_BLKS   BB
#define PREP_BLKS (ZOUT_BLKS + TR_BLKS + CP_BLKS)

// Scratch (device globals — no runtime allocation allowed)
__device__ float  g_fvT[BB*HWN*CC];          // transposed features (B, HW, C)
__device__ float4 g_nearc[BB*HWN];           // compacted valid near pts {x,y,z,|n|^2}
__device__ int    g_near_idx[BB*HWN];        // original index of compacted near pts
__device__ int    g_near_cnt[BB];
__device__ int    g_far_idx[BB*HWN];         // compacted valid+in-range far point indices
__device__ int    g_far_cnt[BB];
__device__ float4 g_ps[BB*SCH*HWN];          // partial top-3 d2 {s0,s1,s2,-} [b][chunk][slot]
__device__ int4   g_pi[BB*SCH*HWN];          // partial top-3 compacted idx {i0,i1,i2,-}
__device__ float  g_cnt[BB*NCELL];           // per-cell point counts

// Sorted-insert of smallest-3, strict '<' so earlier indices win ties
#define INS(val, jj) do {                                             \
    if ((val) < s2) {                                                 \
        if ((val) < s1) {                                             \
            s2 = s1; i2 = i1;                                         \
            if ((val) < s0) { s1 = s0; i1 = i0; s0 = (val); i0 = (jj); } \
            else            { s1 = (val); i1 = (jj); }                \
        } else { s2 = (val); i2 = (jj); }                             \
    }                                                                 \
} while (0)

__device__ __forceinline__ int cell_x(float x) { return (int)floorf(__fdiv_rn(x, 0.1f)); }
__device__ __forceinline__ int cell_y(float y) { return (int)floorf(__fdiv_rn(__fsub_rn(y, -25.6f), 0.1f)); }

// |p|^2 with the reference's rounding: ((x*x + y*y) + z*z), no fma contraction
__device__ __forceinline__ float sqnorm_ref(float x, float y, float z) {
    return __fadd_rn(__fadd_rn(__fmul_rn(x, x), __fmul_rn(y, y)), __fmul_rn(z, z));
}

// GEMM-replica pair distance: acc = rn(a0*b0); acc = fma(a1,b1,acc); acc = fma(a2,b2,acc);
// d2 = rn( rn(fsq+nsq) - acc ).  Pre-doubled f is bit-equal to the alpha=2 folded GEMM.
__device__ __forceinline__ float d2_ref(float fx2, float fy2, float fz2, float fsq,
                                        float nx, float ny, float nz, float nsq) {
    float acc = __fmul_rn(fx2, nx);
    acc = __fmaf_rn(fy2, ny, acc);
    acc = __fmaf_rn(fz2, nz, acc);
    return __fsub_rn(__fadd_rn(fsq, nsq), acc);
}

// ---------------------------------------------------------------------------
// 0. zero g_cnt — MUST be a separate launch: prep's counting atomics would
//    race with same-launch zeroing blocks.
// ---------------------------------------------------------------------------
__global__ void __launch_bounds__(256) zero_cnt_kernel() {
    float4* c4 = (float4*)g_cnt;
    size_t i = (size_t)blockIdx.x * 256 + threadIdx.x;   // 512 blocks
    c4[i] = make_float4(0.f, 0.f, 0.f, 0.f);
}

// ---------------------------------------------------------------------------
// 1. prep: ONE launch, dispatched by block range:
//    [0, 4096)            zero d_out (float4, coalesced)
//    [4096, 5120)         transpose fv (B,C,HW) -> g_fvT (B,HW,C)
//    [5120, 5122)         ordered ballot/scan compaction + cell counting
// ---------------------------------------------------------------------------
__global__ void __launch_bounds__(256) prep_kernel(const float* __restrict__ fv,
                                                   const float* __restrict__ pif,
                                                   const int*   __restrict__ mask,
                                                   const float* __restrict__ piff,
                                                   const int*   __restrict__ maskf,
                                                   float* __restrict__ out) {
    int bid = blockIdx.x;
    int tid = threadIdx.x;

    if (bid < ZOUT_BLKS) {                       // ---- zero d_out ----
        float4* o4 = (float4*)out;
        size_t base = (size_t)bid * 2048 + tid;
        const float4 z = make_float4(0.f, 0.f, 0.f, 0.f);
        #pragma unroll
        for (int i = 0; i < 8; i++)
            o4[base + (size_t)i * 256] = z;
        return;
    }
    bid -= ZOUT_BLKS;

    if (bid < TR_BLKS) {                         // ---- transpose ----
        __shared__ float tile[32][33];
        int b  = bid / ((HWN/32) * (CC/32));
        int r  = bid % ((HWN/32) * (CC/32));
        int c0 = (r / (HWN/32)) * 32;
        int p0 = (r % (HWN/32)) * 32;
        int tx = tid & 31, ty = tid >> 5;        // 32 x 8
        #pragma unroll
        for (int i = ty; i < 32; i += 8)
            tile[i][tx] = fv[((size_t)b*CC + c0 + i) * HWN + p0 + tx];
        __syncthreads();
        #pragma unroll
        for (int i = ty; i < 32; i += 8)
            g_fvT[((size_t)b*HWN + p0 + i) * CC + c0 + tx] = tile[tx][i];
        return;
    }
    bid -= TR_BLKS;

    // ---- compaction + counting (1 block per batch), ballot + block scan ----
    int b = bid;
    int warp = tid >> 5, lane = tid & 31;
    __shared__ unsigned smask[256];              // validity masks, index-ordered chunks
    __shared__ int sscan[256];                   // inclusive scan of popcounts

    // ===== phase A: near (compaction predicate = mask > 0) =====
    const int*   mn = mask + b * HWN;
    const float* pn = pif + (size_t)b * 4 * HWN;
    #pragma unroll 4
    for (int r = 0; r < 32; r++) {
        int p = r * 256 + tid;                   // coalesced
        unsigned m = __ballot_sync(0xffffffffu, mn[p] > 0);
        if (lane == 0) smask[r*8 + warp] = m;    // chunk key = p/32
    }
    __syncthreads();
    sscan[tid] = __popc(smask[tid]);
    __syncthreads();
    #pragma unroll
    for (int off = 1; off < 256; off <<= 1) {
        int v = (tid >= off) ? sscan[tid - off] : 0;
        __syncthreads();
        sscan[tid] += v;
        __syncthreads();
    }
    if (tid == 255) g_near_cnt[b] = sscan[255];
    #pragma unroll 4
    for (int r = 0; r < 32; r++) {
        int p = r * 256 + tid;
        if (mn[p] > 0) {
            int key = r*8 + warp;
            unsigned m = smask[key];
            int rank = sscan[key] - __popc(m) + __popc(m & ((1u << lane) - 1u));
            float x = pn[p], y = pn[HWN + p], z = pn[2*HWN + p];
            g_nearc[b*HWN + rank] = make_float4(x, y, z, sqnorm_ref(x, y, z));
            g_near_idx[b*HWN + rank] = p;
            // count: valid near point that lands in the BEV grid
            int ix = cell_x(x), iy = cell_y(y);
            if (ix >= 0 && ix < NXG && iy >= 0 && iy < NYG)
                atomicAdd(&g_cnt[b*NCELL + iy*NXG + ix], 1.0f);
        }
    }
    __syncthreads();

    // ===== phase B: far (predicate = mask > 0 && cell in range) =====
    const int*   mf  = maskf + b * HWN;
    const float* pff = piff + (size_t)b * 4 * HWN;
    #pragma unroll 4
    for (int r = 0; r < 32; r++) {
        int p = r * 256 + tid;
        bool v = mf[p] > 0;
        if (v) {
            int ix = cell_x(pff[p]), iy = cell_y(pff[HWN + p]);
            v = (ix >= 0 && ix < NXG && iy >= 0 && iy < NYG);
        }
        unsigned m = __ballot_sync(0xffffffffu, v);
        if (lane == 0) smask[r*8 + warp] = m;
    }
    __syncthreads();
    sscan[tid] = __popc(smask[tid]);
    __syncthreads();
    #pragma unroll
    for (int off = 1; off < 256; off <<= 1) {
        int v = (tid >= off) ? sscan[tid - off] : 0;
        __syncthreads();
        sscan[tid] += v;
        __syncthreads();
    }
    if (tid == 255) g_far_cnt[b] = sscan[255];
    #pragma unroll 4
    for (int r = 0; r < 32; r++) {
        int p = r * 256 + tid;
        int key = r*8 + warp;
        unsigned m = smask[key];
        if ((m >> lane) & 1u) {
            int rank = sscan[key] - __popc(m) + __popc(m & ((1u << lane) - 1u));
            g_far_idx[b*HWN + rank] = p;
            int ix = cell_x(pff[p]), iy = cell_y(pff[HWN + p]);
            atomicAdd(&g_cnt[b*NCELL + iy*NXG + ix], 1.0f);
        }
    }
}

// ---------------------------------------------------------------------------
// 2. kNN over compacted near points: thread = far point, small smem chunk
// ---------------------------------------------------------------------------
__global__ void __launch_bounds__(256) knn_kernel(const float* __restrict__ pif_far) {
    __shared__ float4 sh[NCHUNK];
    int b  = blockIdx.z;
    int ch = blockIdx.y;
    int nbase = ch * NCHUNK;
    int ncnt = g_near_cnt[b];
    if (nbase >= ncnt) return;
    if (blockIdx.x * 256 >= g_far_cnt[b]) return;

    int navail = min(NCHUNK, ncnt - nbase);
    int n8 = (navail + 7) & ~7;                  // pad to multiple of 8
    const float4* src = g_nearc + b*HWN + nbase;
    for (int i = threadIdx.x; i < n8; i += 256)
        sh[i] = (i < navail) ? src[i] : make_float4(0.f, 0.f, 0.f, 1e30f);
    __syncthreads();

    int slot = blockIdx.x * 256 + threadIdx.x;
    if (slot >= g_far_cnt[b]) return;
    int p = g_far_idx[b*HWN + slot];

    const float* pf = pif_far + (size_t)b * 4 * HWN;
    float x = pf[p], y = pf[HWN + p], z = pf[2*HWN + p];
    float fsq = sqnorm_ref(x, y, z);
    float fx2 = 2.0f * x, fy2 = 2.0f * y, fz2 = 2.0f * z;  // exact

    float s0 = POS_INF, s1 = POS_INF, s2 = POS_INF;
    int   i0 = 0, i1 = 0, i2 = 0;

    #pragma unroll 1
    for (int j = 0; j < n8; j += 8) {
        float d[8];
        #pragma unroll
        for (int u = 0; u < 8; u++) {
            float4 q = sh[j + u];
            d[u] = d2_ref(fx2, fy2, fz2, fsq, q.x, q.y, q.z, q.w);
        }
        float m = fminf(fminf(fminf(d[0], d[1]), fminf(d[2], d[3])),
                        fminf(fminf(d[4], d[5]), fminf(d[6], d[7])));
        if (m < s2) {   // rarely taken
            #pragma unroll
            for (int u = 0; u < 8; u++) INS(d[u], nbase + j + u);
        }
    }

    int base = (b*SCH + ch) * HWN + slot;
    g_ps[base] = make_float4(s0, s1, s2, 0.0f);
    g_pi[base] = make_int4(i0, i1, i2, 0);
}

// ---------------------------------------------------------------------------
// 3. fused scatter with pre-divided terms: atomicAdd(out, f / cnt[cell]).
//    blockIdx.z = 0: near points (64 lanes/pt).
//    blockIdx.z = 1: far points — warp-parallel top-3 merge, IDW weights
//    (reference rounding), then 64-lane gather+scatter.
// ---------------------------------------------------------------------------
__global__ void __launch_bounds__(256) scatter_kernel(const float* __restrict__ pif_far,
                                                      float* __restrict__ out) {
    int b = blockIdx.y;
    int local = threadIdx.x >> 6;                // point-in-block 0..3
    int lane64 = threadIdx.x & 63;
    int slot = blockIdx.x * 4 + local;

    if (blockIdx.z == 0) {
        if (slot >= g_near_cnt[b]) return;
        float4 q = g_nearc[b*HWN + slot];
        int ix = cell_x(q.x), iy = cell_y(q.y);
        if (ix < 0 || ix >= NXG || iy < 0 || iy >= NYG) return;
        int cell = iy * NXG + ix;
        int p = g_near_idx[b*HWN + slot];
        float c = g_cnt[b*NCELL + cell];         // >= 1 here
        float f = g_fvT[((size_t)b*HWN + p) * CC + lane64];   // coalesced
        atomicAdd(out + (size_t)b*CC*NCELL + (size_t)lane64*NCELL + cell,
                  __fdiv_rn(f, c));
        return;
    }

    // ---- far path ----
    __shared__ float sw[4][3];
    __shared__ int   si[4][3];
    __shared__ int   scell[4];

    int fcnt = g_far_cnt[b];
    bool active = slot < fcnt;
    int half = lane64 >> 5;                      // warp-half within the point
    int lane = lane64 & 31;                      // chunk id for half 0

    if (active && half == 0) {
        // lane = chunk; load this chunk's sorted top-3 partial (or sentinels)
        int ncnt = g_near_cnt[b];
        float a0 = POS_INF, a1 = POS_INF, a2 = POS_INF;
        int   c0 = IDX_INF,  c1 = IDX_INF,  c2 = IDX_INF;
        if (lane * NCHUNK < ncnt) {
            int base = (b*SCH + lane) * HWN + slot;
            float4 v = g_ps[base];
            int4  iv = g_pi[base];
            a0 = v.x; a1 = v.y; a2 = v.z;
            c0 = iv.x; c1 = iv.y; c2 = iv.z;
        }
        // 3-round warp argmin by (value, then compacted index) — identical to
        // sequential INS order (chunks partition ascending indices; within-chunk
        // triples are index-ordered on equal values).
        float S[3]; int I[3];
        #pragma unroll
        for (int k = 0; k < 3; k++) {
            float bv = a0; int bx = c0;
            #pragma unroll
            for (int off = 16; off; off >>= 1) {
                float ov = __shfl_down_sync(0xffffffffu, bv, off);
                int   ox = __shfl_down_sync(0xffffffffu, bx, off);
                if (ov < bv || (ov == bv && ox < bx)) { bv = ov; bx = ox; }
            }
            bv = __shfl_sync(0xffffffffu, bv, 0);
            bx = __shfl_sync(0xffffffffu, bx, 0);
            S[k] = bv; I[k] = bx;
            if (c0 == bx) {                      // unique index -> unique winner
                a0 = a1; c0 = c1; a1 = a2; c1 = c2;
                a2 = POS_INF; c2 = IDX_INF;
            }
        }
        if (lane == 0) {
            // IDW weights exactly as reference: r = 1/(d+1e-8); w = r/((r0+r1)+r2)
            float r0 = __fdiv_rn(1.0f, __fadd_rn(S[0], 1e-8f));
            float r1 = __fdiv_rn(1.0f, __fadd_rn(S[1], 1e-8f));
            float r2 = __fdiv_rn(1.0f, __fadd_rn(S[2], 1e-8f));
            float rs = __fadd_rn(__fadd_rn(r0, r1), r2);
            sw[local][0] = __fdiv_rn(r0, rs);
            sw[local][1] = __fdiv_rn(r1, rs);
            sw[local][2] = __fdiv_rn(r2, rs);
            si[local][0] = g_near_idx[b*HWN + I[0]];
            si[local][1] = g_near_idx[b*HWN + I[1]];
            si[local][2] = g_near_idx[b*HWN + I[2]];
            int p = g_far_idx[b*HWN + slot];
            const float* pf = pif_far + (size_t)b * 4 * HWN;
            int ix = cell_x(pf[p]), iy = cell_y(pf[HWN + p]);  // in range by compaction
            scell[local] = iy * NXG + ix;
        }
    }
    __syncthreads();
    if (!active) return;

    float w0 = sw[local][0], w1 = sw[local][1], w2 = sw[local][2];
    int   j0 = si[local][0], j1 = si[local][1], j2 = si[local][2];
    int cell = scell[local];
    float c = g_cnt[b*NCELL + cell];             // >= 1 here
    const float* fT = g_fvT + (size_t)b*HWN*CC;
    // einsum order: (w0*g0 + w1*g1) + w2*g2, no fma
    float f = __fadd_rn(__fadd_rn(__fmul_rn(w0, fT[(size_t)j0*CC + lane64]),
                                  __fmul_rn(w1, fT[(size_t)j1*CC + lane64])),
                        __fmul_rn(w2, fT[(size_t)j2*CC + lane64]));
    atomicAdd(out + (size_t)b*CC*NCELL + (size_t)lane64*NCELL + cell,
              __fdiv_rn(f, c));
}

extern "C" void kernel_launch(void* const* d_in, const int* in_sizes, int n_in,
                              void* d_out, int out_size) {
    const float* fv    = (const float*)d_in[0];   // (B,C,H,W)
    const float* pif   = (const float*)d_in[1];   // (B,4,H,W)
    const int*   mask  = (const int*)  d_in[2];   // (B,H,W)
    const float* piff  = (const float*)d_in[3];   // (B,4,H,W)
    const int*   maskf = (const int*)  d_in[4];   // (B,H,W)
    float* out = (float*)d_out;                   // (B,C,NY,NX)

    zero_cnt_kernel<<<BB*NCELL/4/256, 256>>>();

    prep_kernel<<<PREP_BLKS, 256>>>(fv, pif, mask, piff, maskf, out);

    knn_kernel<<<dim3(HWN/256, SCH, BB), 256>>>(piff);

    scatter_kernel<<<dim3(HWN/4, BB, 2), 256>>>(piff, out);
}